// round 9
// baseline (speedup 1.0000x reference)
#include <cuda_runtime.h>
#include <cuda_bf16.h>
#include <mma.h>
#include <math.h>
using namespace nvcuda;

#define BB 128
#define SSN 256
#define TTN 256
#define UU 512
#define GG 2048
#define TI_T 257
#define BU (BB * UU)

typedef __nv_bfloat16 bf16;

__device__ float g_xproj[(size_t)TTN * BB * GG];
__device__ float g_h[(size_t)(TTN + 1) * BU];
__device__ float g_c[(size_t)BU];
__device__ float g_zpart[(size_t)8 * BB * GG];
__device__ bf16 g_hbh[(size_t)(TTN + 1) * BU], g_hbl[(size_t)(TTN + 1) * BU];
__device__ bf16 g_wbh[(size_t)TTN * BU], g_wbl[(size_t)TTN * BU];
__device__ bf16 g_tih[(size_t)TTN * BU], g_til[(size_t)TTN * BU];
__device__ bf16 g_wkh[(size_t)UU * GG], g_wkl[(size_t)UU * GG];
__device__ bf16 g_rkh[(size_t)UU * GG], g_rkl[(size_t)UU * GG];
__device__ bf16 g_wah[(size_t)2 * UU * UU], g_wal[(size_t)2 * UU * UU];
__device__ volatile unsigned g_flags[128];
__device__ volatile unsigned g_phase;

__device__ __forceinline__ void split2(float x, bf16& h, bf16& l) {
    h = __float2bfloat16(x);
    l = __float2bfloat16(x - __bfloat162float(h));
}

__global__ void init_kernel(const float* __restrict__ h0, const float* __restrict__ c0) {
    int i = blockIdx.x * blockDim.x + threadIdx.x;
    float v = h0[i];
    g_h[i] = v;
    split2(v, g_hbh[i], g_hbl[i]);
    g_c[i] = c0[i];
    if (blockIdx.x == 0) {
        if (threadIdx.x < 128) g_flags[threadIdx.x] = 0;
        if (threadIdx.x == 128) g_phase = 0;
    }
}

__global__ void cvt_kernel(const float* __restrict__ src, bf16* __restrict__ hi, bf16* __restrict__ lo) {
    int i = blockIdx.x * 256 + threadIdx.x;
    split2(src[i], hi[i], lo[i]);
}

__global__ void cvt_ti_kernel(const float* __restrict__ ti) {
    int i = blockIdx.x * 256 + threadIdx.x;
    int u = i & 511, b = (i >> 9) & 127, t = i >> 16;
    float x = ti[(size_t)b * (TI_T * UU) + (size_t)t * UU + u];
    split2(x, g_tih[i], g_til[i]);
}

// ---------------- WMMA 128x128 tile machinery (one-shot GEMMs) ----------------
#define WMMA_DECLS \
    const int tid = threadIdx.x; \
    const int wid = tid >> 5; \
    const int wm = (wid >> 2) * 64, wn = (wid & 3) * 32; \
    wmma::fragment<wmma::accumulator, 16, 16, 16, float> facc[4][2]; \
    _Pragma("unroll") for (int i = 0; i < 4; i++) \
    _Pragma("unroll") for (int j = 0; j < 2; j++) wmma::fill_fragment(facc[i][j], 0.f);

#define WMMA_SMEM \
    __shared__ bf16 sAh[128][24], sAl[128][24]; \
    __shared__ bf16 sBh[16][136], sBl[16][136];

#define STAGE(AH, AL, ASTRIDE, BH, BL, BSTRIDE) { \
    __syncthreads(); \
    int r = tid >> 1, c8 = (tid & 1) * 8; \
    *(uint4*)&sAh[r][c8] = *(const uint4*)((AH) + (size_t)r * (ASTRIDE) + c8); \
    *(uint4*)&sAl[r][c8] = *(const uint4*)((AL) + (size_t)r * (ASTRIDE) + c8); \
    int kr = tid >> 4, nc8 = (tid & 15) * 8; \
    *(uint4*)&sBh[kr][nc8] = *(const uint4*)((BH) + (size_t)kr * (BSTRIDE) + nc8); \
    *(uint4*)&sBl[kr][nc8] = *(const uint4*)((BL) + (size_t)kr * (BSTRIDE) + nc8); \
    __syncthreads(); }

#define WMMA_CHUNK { \
    wmma::fragment<wmma::matrix_a, 16, 16, 16, bf16, wmma::row_major> ah[4], al[4]; \
    wmma::fragment<wmma::matrix_b, 16, 16, 16, bf16, wmma::row_major> bh[2], bl[2]; \
    _Pragma("unroll") for (int i = 0; i < 4; i++) { \
        wmma::load_matrix_sync(ah[i], &sAh[wm + i * 16][0], 24); \
        wmma::load_matrix_sync(al[i], &sAl[wm + i * 16][0], 24); } \
    _Pragma("unroll") for (int j = 0; j < 2; j++) { \
        wmma::load_matrix_sync(bh[j], &sBh[0][wn + j * 16], 136); \
        wmma::load_matrix_sync(bl[j], &sBl[0][wn + j * 16], 136); } \
    _Pragma("unroll") for (int i = 0; i < 4; i++) \
    _Pragma("unroll") for (int j = 0; j < 2; j++) { \
        wmma::mma_sync(facc[i][j], ah[i], bh[j], facc[i][j]); \
        wmma::mma_sync(facc[i][j], ah[i], bl[j], facc[i][j]); \
        wmma::mma_sync(facc[i][j], al[i], bh[j], facc[i][j]); } }

#define WMMA_STORE(BASE, LD) \
    _Pragma("unroll") for (int i = 0; i < 4; i++) \
    _Pragma("unroll") for (int j = 0; j < 2; j++) \
        wmma::store_matrix_sync((BASE) + (size_t)(wm + i * 16) * (LD) + wn + j * 16, \
                                facc[i][j], (LD), wmma::mem_row_major);

__global__ __launch_bounds__(256) void xproj_kernel() {
    WMMA_SMEM
    WMMA_DECLS
    const int t = blockIdx.y, n0 = blockIdx.x * 128;
    const bf16* Ah = g_tih + (size_t)t * BU;
    const bf16* Al = g_til + (size_t)t * BU;
    for (int k0 = 0; k0 < UU; k0 += 16) {
        STAGE(Ah + k0, Al + k0, UU,
              g_wkh + (size_t)k0 * GG + n0, g_wkl + (size_t)k0 * GG + n0, GG)
        WMMA_CHUNK
    }
    WMMA_STORE(g_xproj + (size_t)t * (BB * GG) + n0, GG)
}

__device__ __forceinline__ float sigm(float x) { return 1.f / (1.f + expf(-x)); }

__device__ __forceinline__ void grid_barrier(unsigned gen) {
    __syncthreads();
    if (threadIdx.x == 0) {
        __threadfence();
        g_flags[blockIdx.x] = gen;
    }
    if (blockIdx.x == 0) {
        bool done = false;
        do {
            bool ok = (threadIdx.x < 128) ? (g_flags[threadIdx.x] >= gen) : true;
            done = __syncthreads_and(ok);
        } while (!done);
        if (threadIdx.x == 0) { __threadfence(); g_phase = gen; }
    } else {
        if (threadIdx.x == 0) {
            while (g_phase < gen) { }
            __threadfence();
        }
        __syncthreads();
    }
}

// Persistent recurrence, R-resident smem.
// Dyn smem (bf16 elems): sAh[128][72] @0, sAl @9216, sRh[64][136] @18432, sRl @27136.
#define REC_SMEM_BYTES ((18432 + 2 * 64 * 136) * 2)   // 71680 B

__global__ __launch_bounds__(256) void recurrence_kernel(const float* __restrict__ bias) {
    extern __shared__ bf16 rs[];
    bf16* sAh = rs;
    bf16* sAl = rs + 9216;
    bf16* sRh = rs + 18432;
    bf16* sRl = rs + 27136;
    const int tid = threadIdx.x;
    const int wid = tid >> 5;
    const int wm = (wid >> 2) * 64, wn = (wid & 3) * 32;
    const int ct = blockIdx.x & 15, split = blockIdx.x >> 4;
    const int gc0 = ct * 128, ks = split * 64;

    // Load this block's R tile (64K x 128N, hi+lo) once.
#pragma unroll
    for (int i = 0; i < 4; i++) {
        int idx = tid + i * 256;
        int kr = idx >> 4, c8 = (idx & 15) * 8;
        *(uint4*)&sRh[kr * 136 + c8] = *(const uint4*)&g_rkh[(size_t)(ks + kr) * GG + gc0 + c8];
        *(uint4*)&sRl[kr * 136 + c8] = *(const uint4*)&g_rkl[(size_t)(ks + kr) * GG + gc0 + c8];
    }

    // phase-B mapping: (b, 2 consecutive u); bias preloaded
    const int gidx = blockIdx.x * 256 + tid;
    const int gb = gidx >> 8, gu = (gidx & 255) << 1;
    const float2 bi = *(const float2*)(bias + gu);
    const float2 bfg = *(const float2*)(bias + 512 + gu);
    const float2 bg = *(const float2*)(bias + 1024 + gu);
    const float2 bo = *(const float2*)(bias + 1536 + gu);
    unsigned gen = 0;

    for (int t = 0; t < TTN; t++) {
        // ---- phase A: stage h tile, MMA against resident R ----
        __syncthreads();   // t=0: R loaded; t>0: prior-step frag reads done
        {
            const bf16* Ah = g_hbh + (size_t)t * BU + ks;
            const bf16* Al = g_hbl + (size_t)t * BU + ks;
#pragma unroll
            for (int i = 0; i < 4; i++) {
                int idx = tid + i * 256;
                int r = idx >> 3, c8 = (idx & 7) * 8;
                *(uint4*)&sAh[r * 72 + c8] = *(const uint4*)(Ah + (size_t)r * UU + c8);
                *(uint4*)&sAl[r * 72 + c8] = *(const uint4*)(Al + (size_t)r * UU + c8);
            }
        }
        __syncthreads();
        {
            wmma::fragment<wmma::accumulator, 16, 16, 16, float> facc[4][2];
#pragma unroll
            for (int i = 0; i < 4; i++)
#pragma unroll
                for (int j = 0; j < 2; j++) wmma::fill_fragment(facc[i][j], 0.f);
#pragma unroll
            for (int kc = 0; kc < 4; kc++) {
                wmma::fragment<wmma::matrix_a, 16, 16, 16, bf16, wmma::row_major> ah[4], al[4];
                wmma::fragment<wmma::matrix_b, 16, 16, 16, bf16, wmma::row_major> bh[2], bl[2];
#pragma unroll
                for (int i = 0; i < 4; i++) {
                    wmma::load_matrix_sync(ah[i], &sAh[(wm + i * 16) * 72 + kc * 16], 72);
                    wmma::load_matrix_sync(al[i], &sAl[(wm + i * 16) * 72 + kc * 16], 72);
                }
#pragma unroll
                for (int j = 0; j < 2; j++) {
                    wmma::load_matrix_sync(bh[j], &sRh[(kc * 16) * 136 + wn + j * 16], 136);
                    wmma::load_matrix_sync(bl[j], &sRl[(kc * 16) * 136 + wn + j * 16], 136);
                }
#pragma unroll
                for (int i = 0; i < 4; i++)
#pragma unroll
                    for (int j = 0; j < 2; j++) {
                        wmma::mma_sync(facc[i][j], ah[i], bh[j], facc[i][j]);
                        wmma::mma_sync(facc[i][j], ah[i], bl[j], facc[i][j]);
                        wmma::mma_sync(facc[i][j], al[i], bh[j], facc[i][j]);
                    }
            }
            float* zbase = g_zpart + (size_t)split * (BB * GG) + gc0;
#pragma unroll
            for (int i = 0; i < 4; i++)
#pragma unroll
                for (int j = 0; j < 2; j++)
                    wmma::store_matrix_sync(zbase + (size_t)(wm + i * 16) * GG + wn + j * 16,
                                            facc[i][j], GG, wmma::mem_row_major);
        }
        grid_barrier(++gen);
        // ---- phase B: gates ----
        {
            const float* xp = g_xproj + (size_t)t * (BB * GG) + (size_t)gb * GG + gu;
            float2 zi = *(const float2*)(xp);
            float2 zf = *(const float2*)(xp + 512);
            float2 zg = *(const float2*)(xp + 1024);
            float2 zo = *(const float2*)(xp + 1536);
#pragma unroll
            for (int s = 0; s < 8; s++) {
                const float* zp = g_zpart + (size_t)s * (BB * GG) + (size_t)gb * GG + gu;
                float2 a = __ldcg((const float2*)(zp));
                float2 f = __ldcg((const float2*)(zp + 512));
                float2 g = __ldcg((const float2*)(zp + 1024));
                float2 o = __ldcg((const float2*)(zp + 1536));
                zi.x += a.x; zi.y += a.y;
                zf.x += f.x; zf.y += f.y;
                zg.x += g.x; zg.y += g.y;
                zo.x += o.x; zo.y += o.y;
            }
            zi.x += bi.x; zi.y += bi.y;
            zf.x += bfg.x; zf.y += bfg.y;
            zg.x += bg.x; zg.y += bg.y;
            zo.x += bo.x; zo.y += bo.y;
            float* cp = g_c + (size_t)gb * UU + gu;
            float2 c = *(const float2*)cp;
            float2 cn, hn;
            cn.x = sigm(zf.x) * c.x + sigm(zi.x) * tanhf(zg.x);
            cn.y = sigm(zf.y) * c.y + sigm(zi.y) * tanhf(zg.y);
            hn.x = sigm(zo.x) * tanhf(cn.x);
            hn.y = sigm(zo.y) * tanhf(cn.y);
            *(float2*)cp = cn;
            size_t hidx = (size_t)(t + 1) * BU + (size_t)gb * UU + gu;
            *(float2*)&g_h[hidx] = hn;
            split2(hn.x, g_hbh[hidx], g_hbl[hidx]);
            split2(hn.y, g_hbh[hidx + 1], g_hbl[hidx + 1]);
        }
        grid_barrier(++gen);
    }
}

// Attention (fp32): block = (16 timesteps, one batch). Writes context as bf16 hi/lo.
#define HPAD 20
#define SCP 264
#define S1P 260
#define ATTN_SMEM_BYTES (18624 * 4)

__global__ __launch_bounds__(256) void attn_kernel(const float* __restrict__ SRC) {
    extern __shared__ float sm[];
    float* sHT = sm;
    float* sSc = sm + 10240;
    float* sS1 = sm + 14464;
    const int tid = threadIdx.x;
    const int t0 = blockIdx.x * 16, b = blockIdx.y;
    const float* src = SRC + (size_t)b * (SSN * UU);
#pragma unroll
    for (int i = 0; i < 8; i++) {
        int f4 = tid + i*256, tt = f4 >> 7, kq = f4 & 127;
        float4 v = *(const float4*)&g_h[(size_t)(t0+tt+1)*BU + (size_t)b*UU + kq*4];
        sHT[(kq*4+0)*HPAD+tt] = v.x; sHT[(kq*4+1)*HPAD+tt] = v.y;
        sHT[(kq*4+2)*HPAD+tt] = v.z; sHT[(kq*4+3)*HPAD+tt] = v.w;
    }
    __syncthreads();
    const int tg = tid >> 6, sg = tid & 63;
    float acc[4][4];
#pragma unroll
    for (int i = 0; i < 4; i++)
#pragma unroll
        for (int j = 0; j < 4; j++) acc[i][j] = 0.f;
    for (int k0 = 0; k0 < UU; k0 += 16) {
#pragma unroll
        for (int i = 0; i < 4; i++) {
            int f4 = tid + i*256, s = f4 >> 2, kq = f4 & 3;
            float4 v = *(const float4*)&src[(size_t)s*UU + k0 + kq*4];
            sS1[(kq*4+0)*S1P+s] = v.x; sS1[(kq*4+1)*S1P+s] = v.y;
            sS1[(kq*4+2)*S1P+s] = v.z; sS1[(kq*4+3)*S1P+s] = v.w;
        }
        __syncthreads();
#pragma unroll
        for (int kk = 0; kk < 16; kk++) {
            float4 hv = *(const float4*)&sHT[(k0+kk)*HPAD + tg*4];
            float4 sv = *(const float4*)&sS1[kk*S1P + sg*4];
            float hr[4] = {hv.x,hv.y,hv.z,hv.w};
            float sr[4] = {sv.x,sv.y,sv.z,sv.w};
#pragma unroll
            for (int i = 0; i < 4; i++)
#pragma unroll
                for (int j = 0; j < 4; j++) acc[i][j] += hr[i]*sr[j];
        }
        __syncthreads();
    }
#pragma unroll
    for (int i = 0; i < 4; i++)
#pragma unroll
        for (int j = 0; j < 4; j++) sSc[(tg*4+i)*SCP + sg*4+j] = acc[i][j];
    __syncthreads();
    {
        const int w = tid >> 5, lane = tid & 31;
#pragma unroll
        for (int rr = 0; rr < 2; rr++) {
            int row = w*2 + rr;
            float v[8], m = -1e30f;
#pragma unroll
            for (int q = 0; q < 8; q++) { v[q] = sSc[row*SCP + lane + q*32]; m = fmaxf(m, v[q]); }
#pragma unroll
            for (int o = 16; o > 0; o >>= 1) m = fmaxf(m, __shfl_xor_sync(0xffffffffu, m, o));
            float ssum = 0.f;
#pragma unroll
            for (int q = 0; q < 8; q++) { v[q] = expf(v[q] - m); ssum += v[q]; }
#pragma unroll
            for (int o = 16; o > 0; o >>= 1) ssum += __shfl_xor_sync(0xffffffffu, ssum, o);
            float inv = 1.f / ssum;
#pragma unroll
            for (int q = 0; q < 8; q++) sSc[row*SCP + lane + q*32] = v[q] * inv;
        }
    }
    __syncthreads();
    float* sSrc = sm;
    const int ug = tid & 63;
    float acc2[4][8];
#pragma unroll
    for (int i = 0; i < 4; i++)
#pragma unroll
        for (int j = 0; j < 8; j++) acc2[i][j] = 0.f;
    for (int s0 = 0; s0 < SSN; s0 += 16) {
        __syncthreads();
#pragma unroll
        for (int i = 0; i < 8; i++) {
            int f4 = tid + i*256, si = f4 >> 7, uq = f4 & 127;
            *(float4*)&sSrc[si*UU + uq*4] = *(const float4*)&src[(size_t)(s0+si)*UU + uq*4];
        }
        __syncthreads();
#pragma unroll
        for (int si = 0; si < 16; si++) {
            float ar[4];
#pragma unroll
            for (int i = 0; i < 4; i++) ar[i] = sSc[(tg*4+i)*SCP + s0 + si];
            float4 u0 = *(const float4*)&sSrc[si*UU + ug*8];
            float4 u1 = *(const float4*)&sSrc[si*UU + ug*8 + 4];
            float ur[8] = {u0.x,u0.y,u0.z,u0.w,u1.x,u1.y,u1.z,u1.w};
#pragma unroll
            for (int i = 0; i < 4; i++)
#pragma unroll
                for (int j = 0; j < 8; j++) acc2[i][j] += ar[i]*ur[j];
        }
    }
#pragma unroll
    for (int i = 0; i < 4; i++) {
        size_t base = ((size_t)(t0 + tg*4 + i) * BB + b) * UU + ug*8;
#pragma unroll
        for (int j = 0; j < 8; j++)
            split2(acc2[i][j], g_wbh[base + j], g_wbl[base + j]);
    }
}

__global__ __launch_bounds__(256) void final_gemm(float* __restrict__ out) {
    WMMA_SMEM
    WMMA_DECLS
    const int t = blockIdx.y, n0 = blockIdx.x * 128;
    for (int k0 = 0; k0 < 1024; k0 += 16) {
        const bf16* Ah;
        const bf16* Al;
        int kc;
        if (k0 < 512) { Ah = g_hbh + (size_t)(t+1) * BU; Al = g_hbl + (size_t)(t+1) * BU; kc = k0; }
        else          { Ah = g_wbh + (size_t)t * BU;     Al = g_wbl + (size_t)t * BU;     kc = k0 - 512; }
        STAGE(Ah + kc, Al + kc, UU,
              g_wah + (size_t)k0 * UU + n0, g_wal + (size_t)k0 * UU + n0, UU)
        WMMA_CHUNK
    }
    WMMA_STORE(out + (size_t)t * UU + n0, (size_t)(TTN * UU))
}

__global__ void tanh_kernel(float* __restrict__ out) {
    int i = blockIdx.x * 256 + threadIdx.x;
    float4 v = ((float4*)out)[i];
    v.x = tanhf(v.x); v.y = tanhf(v.y); v.z = tanhf(v.z); v.w = tanhf(v.w);
    ((float4*)out)[i] = v;
}

extern "C" void kernel_launch(void* const* d_in, const int* in_sizes, int n_in,
                              void* d_out, int out_size) {
    (void)in_sizes; (void)n_in; (void)out_size;
    const float* h0   = (const float*)d_in[0];
    const float* c0   = (const float*)d_in[1];
    const float* src  = (const float*)d_in[2];
    const float* ti   = (const float*)d_in[3];
    const float* W    = (const float*)d_in[4];
    const float* Rk   = (const float*)d_in[5];
    const float* bias = (const float*)d_in[6];
    const float* Wa   = (const float*)d_in[7];
    float* out = (float*)d_out;

    cudaFuncSetAttribute(attn_kernel, cudaFuncAttributeMaxDynamicSharedMemorySize,
                         ATTN_SMEM_BYTES);
    cudaFuncSetAttribute(recurrence_kernel, cudaFuncAttributeMaxDynamicSharedMemorySize,
                         REC_SMEM_BYTES);

    init_kernel<<<256, 256>>>(h0, c0);
    bf16 *wkh, *wkl, *rkh, *rkl, *wah, *wal;
    cudaGetSymbolAddress((void**)&wkh, g_wkh); cudaGetSymbolAddress((void**)&wkl, g_wkl);
    cudaGetSymbolAddress((void**)&rkh, g_rkh); cudaGetSymbolAddress((void**)&rkl, g_rkl);
    cudaGetSymbolAddress((void**)&wah, g_wah); cudaGetSymbolAddress((void**)&wal, g_wal);
    cvt_kernel<<<4096, 256>>>(W, wkh, wkl);
    cvt_kernel<<<4096, 256>>>(Rk, rkh, rkl);
    cvt_kernel<<<2048, 256>>>(Wa, wah, wal);
    cvt_ti_kernel<<<65536, 256>>>(ti);

    xproj_kernel<<<dim3(16, 256), 256>>>();
    recurrence_kernel<<<128, 256, REC_SMEM_BYTES>>>(bias);
    attn_kernel<<<dim3(16, 128), 256, ATTN_SMEM_BYTES>>>(src);
    final_gemm<<<dim3(4, 256), 256>>>(out);
    tanh_kernel<<<16384, 256>>>(out);
}

// round 12
// speedup vs baseline: 1.1116x; 1.1116x over previous
#include <cuda_runtime.h>
#include <cuda_bf16.h>
#include <mma.h>
#include <math.h>
using namespace nvcuda;

#define BB 128
#define SSN 256
#define TTN 256
#define UU 512
#define GG 2048
#define TI_T 257
#define BU (BB * UU)

typedef __nv_bfloat16 bf16;

__device__ float g_xproj[(size_t)TTN * BB * GG];
__device__ float g_c[(size_t)BU];
__device__ float g_zpart[(size_t)8 * BB * GG];
__device__ bf16 g_hbh[(size_t)(TTN + 1) * BU], g_hbl[(size_t)(TTN + 1) * BU];
__device__ bf16 g_wbh[(size_t)TTN * BU], g_wbl[(size_t)TTN * BU];
__device__ bf16 g_tih[(size_t)TTN * BU], g_til[(size_t)TTN * BU];
__device__ bf16 g_srcbh[(size_t)BB * SSN * UU], g_srcbl[(size_t)BB * SSN * UU];
__device__ bf16 g_wkh[(size_t)UU * GG], g_wkl[(size_t)UU * GG];
__device__ bf16 g_rkh[(size_t)UU * GG], g_rkl[(size_t)UU * GG];
__device__ bf16 g_wah[(size_t)2 * UU * UU], g_wal[(size_t)2 * UU * UU];
__device__ volatile unsigned g_flags[128];

__device__ __forceinline__ void split2(float x, bf16& h, bf16& l) {
    h = __float2bfloat16(x);
    l = __float2bfloat16(x - __bfloat162float(h));
}

__global__ void init_kernel(const float* __restrict__ h0, const float* __restrict__ c0) {
    int i = blockIdx.x * blockDim.x + threadIdx.x;
    split2(h0[i], g_hbh[i], g_hbl[i]);
    g_c[i] = c0[i];
    if (blockIdx.x == 0 && threadIdx.x < 128) g_flags[threadIdx.x] = 0;
}

__global__ void cvt_kernel(const float* __restrict__ src, bf16* __restrict__ hi, bf16* __restrict__ lo) {
    int i = blockIdx.x * 256 + threadIdx.x;
    split2(src[i], hi[i], lo[i]);
}

__global__ void cvt_ti_kernel(const float* __restrict__ ti) {
    int i = blockIdx.x * 256 + threadIdx.x;
    int u = i & 511, b = (i >> 9) & 127, t = i >> 16;
    float x = ti[(size_t)b * (TI_T * UU) + (size_t)t * UU + u];
    split2(x, g_tih[i], g_til[i]);
}

// ---------------- WMMA 128x128 tile machinery (one-shot GEMMs) ----------------
#define WMMA_DECLS \
    const int tid = threadIdx.x; \
    const int wid = tid >> 5; \
    const int wm = (wid >> 2) * 64, wn = (wid & 3) * 32; \
    wmma::fragment<wmma::accumulator, 16, 16, 16, float> facc[4][2]; \
    _Pragma("unroll") for (int i = 0; i < 4; i++) \
    _Pragma("unroll") for (int j = 0; j < 2; j++) wmma::fill_fragment(facc[i][j], 0.f);

#define WMMA_SMEM \
    __shared__ bf16 sAh[128][24], sAl[128][24]; \
    __shared__ bf16 sBh[16][136], sBl[16][136];

#define STAGE(AH, AL, ASTRIDE, BH, BL, BSTRIDE) { \
    __syncthreads(); \
    int r = tid >> 1, c8 = (tid & 1) * 8; \
    *(uint4*)&sAh[r][c8] = *(const uint4*)((AH) + (size_t)r * (ASTRIDE) + c8); \
    *(uint4*)&sAl[r][c8] = *(const uint4*)((AL) + (size_t)r * (ASTRIDE) + c8); \
    int kr = tid >> 4, nc8 = (tid & 15) * 8; \
    *(uint4*)&sBh[kr][nc8] = *(const uint4*)((BH) + (size_t)kr * (BSTRIDE) + nc8); \
    *(uint4*)&sBl[kr][nc8] = *(const uint4*)((BL) + (size_t)kr * (BSTRIDE) + nc8); \
    __syncthreads(); }

#define WMMA_CHUNK { \
    wmma::fragment<wmma::matrix_a, 16, 16, 16, bf16, wmma::row_major> ah[4], al[4]; \
    wmma::fragment<wmma::matrix_b, 16, 16, 16, bf16, wmma::row_major> bh[2], bl[2]; \
    _Pragma("unroll") for (int i = 0; i < 4; i++) { \
        wmma::load_matrix_sync(ah[i], &sAh[wm + i * 16][0], 24); \
        wmma::load_matrix_sync(al[i], &sAl[wm + i * 16][0], 24); } \
    _Pragma("unroll") for (int j = 0; j < 2; j++) { \
        wmma::load_matrix_sync(bh[j], &sBh[0][wn + j * 16], 136); \
        wmma::load_matrix_sync(bl[j], &sBl[0][wn + j * 16], 136); } \
    _Pragma("unroll") for (int i = 0; i < 4; i++) \
    _Pragma("unroll") for (int j = 0; j < 2; j++) { \
        wmma::mma_sync(facc[i][j], ah[i], bh[j], facc[i][j]); \
        wmma::mma_sync(facc[i][j], ah[i], bl[j], facc[i][j]); \
        wmma::mma_sync(facc[i][j], al[i], bh[j], facc[i][j]); } }

#define WMMA_STORE(BASE, LD) \
    _Pragma("unroll") for (int i = 0; i < 4; i++) \
    _Pragma("unroll") for (int j = 0; j < 2; j++) \
        wmma::store_matrix_sync((BASE) + (size_t)(wm + i * 16) * (LD) + wn + j * 16, \
                                facc[i][j], (LD), wmma::mem_row_major);

__global__ __launch_bounds__(256) void xproj_kernel() {
    WMMA_SMEM
    WMMA_DECLS
    const int t = blockIdx.y, n0 = blockIdx.x * 128;
    const bf16* Ah = g_tih + (size_t)t * BU;
    const bf16* Al = g_til + (size_t)t * BU;
    for (int k0 = 0; k0 < UU; k0 += 16) {
        STAGE(Ah + k0, Al + k0, UU,
              g_wkh + (size_t)k0 * GG + n0, g_wkl + (size_t)k0 * GG + n0, GG)
        WMMA_CHUNK
    }
    WMMA_STORE(g_xproj + (size_t)t * (BB * GG) + n0, GG)
}

__device__ __forceinline__ float sigm(float x) { return 1.f / (1.f + expf(-x)); }

// Flat grid barrier: every block polls all 128 flags (one L2 hop).
__device__ __forceinline__ void grid_barrier(unsigned gen) {
    __syncthreads();
    if (threadIdx.x == 0) {
        __threadfence();
        g_flags[blockIdx.x] = gen;
    }
    bool done = false;
    do {
        bool ok = (threadIdx.x < 128) ? (g_flags[threadIdx.x] >= gen) : true;
        done = __syncthreads_and(ok);
    } while (!done);
    __threadfence();
}

// Persistent recurrence, R-resident smem.
#define REC_SMEM_BYTES ((18432 + 2 * 64 * 136) * 2)   // 71680 B

__global__ __launch_bounds__(256) void recurrence_kernel(const float* __restrict__ bias) {
    extern __shared__ bf16 rs[];
    bf16* sAh = rs;
    bf16* sAl = rs + 9216;
    bf16* sRh = rs + 18432;
    bf16* sRl = rs + 27136;
    const int tid = threadIdx.x;
    const int wid = tid >> 5;
    const int wm = (wid >> 2) * 64, wn = (wid & 3) * 32;
    const int ct = blockIdx.x & 15, split = blockIdx.x >> 4;
    const int gc0 = ct * 128, ks = split * 64;

#pragma unroll
    for (int i = 0; i < 4; i++) {
        int idx = tid + i * 256;
        int kr = idx >> 4, c8 = (idx & 15) * 8;
        *(uint4*)&sRh[kr * 136 + c8] = *(const uint4*)&g_rkh[(size_t)(ks + kr) * GG + gc0 + c8];
        *(uint4*)&sRl[kr * 136 + c8] = *(const uint4*)&g_rkl[(size_t)(ks + kr) * GG + gc0 + c8];
    }

    const int gidx = blockIdx.x * 256 + tid;
    const int gb = gidx >> 8, gu = (gidx & 255) << 1;
    const float2 bi = *(const float2*)(bias + gu);
    const float2 bfg = *(const float2*)(bias + 512 + gu);
    const float2 bg = *(const float2*)(bias + 1024 + gu);
    const float2 bo = *(const float2*)(bias + 1536 + gu);
    unsigned gen = 0;

    for (int t = 0; t < TTN; t++) {
        __syncthreads();
        {
            const bf16* Ah = g_hbh + (size_t)t * BU + ks;
            const bf16* Al = g_hbl + (size_t)t * BU + ks;
#pragma unroll
            for (int i = 0; i < 4; i++) {
                int idx = tid + i * 256;
                int r = idx >> 3, c8 = (idx & 7) * 8;
                *(uint4*)&sAh[r * 72 + c8] = *(const uint4*)(Ah + (size_t)r * UU + c8);
                *(uint4*)&sAl[r * 72 + c8] = *(const uint4*)(Al + (size_t)r * UU + c8);
            }
        }
        __syncthreads();
        {
            wmma::fragment<wmma::accumulator, 16, 16, 16, float> facc[4][2];
#pragma unroll
            for (int i = 0; i < 4; i++)
#pragma unroll
                for (int j = 0; j < 2; j++) wmma::fill_fragment(facc[i][j], 0.f);
#pragma unroll
            for (int kc = 0; kc < 4; kc++) {
                wmma::fragment<wmma::matrix_a, 16, 16, 16, bf16, wmma::row_major> ah[4], al[4];
                wmma::fragment<wmma::matrix_b, 16, 16, 16, bf16, wmma::row_major> bh[2], bl[2];
#pragma unroll
                for (int i = 0; i < 4; i++) {
                    wmma::load_matrix_sync(ah[i], &sAh[(wm + i * 16) * 72 + kc * 16], 72);
                    wmma::load_matrix_sync(al[i], &sAl[(wm + i * 16) * 72 + kc * 16], 72);
                }
#pragma unroll
                for (int j = 0; j < 2; j++) {
                    wmma::load_matrix_sync(bh[j], &sRh[(kc * 16) * 136 + wn + j * 16], 136);
                    wmma::load_matrix_sync(bl[j], &sRl[(kc * 16) * 136 + wn + j * 16], 136);
                }
#pragma unroll
                for (int i = 0; i < 4; i++)
#pragma unroll
                    for (int j = 0; j < 2; j++) {
                        wmma::mma_sync(facc[i][j], ah[i], bh[j], facc[i][j]);
                        wmma::mma_sync(facc[i][j], ah[i], bl[j], facc[i][j]);
                        wmma::mma_sync(facc[i][j], al[i], bh[j], facc[i][j]);
                    }
            }
            float* zbase = g_zpart + (size_t)split * (BB * GG) + gc0;
#pragma unroll
            for (int i = 0; i < 4; i++)
#pragma unroll
                for (int j = 0; j < 2; j++)
                    wmma::store_matrix_sync(zbase + (size_t)(wm + i * 16) * GG + wn + j * 16,
                                            facc[i][j], GG, wmma::mem_row_major);
        }
        grid_barrier(++gen);
        {
            const float* xp = g_xproj + (size_t)t * (BB * GG) + (size_t)gb * GG + gu;
            float2 zi = *(const float2*)(xp);
            float2 zf = *(const float2*)(xp + 512);
            float2 zg = *(const float2*)(xp + 1024);
            float2 zo = *(const float2*)(xp + 1536);
#pragma unroll
            for (int s = 0; s < 8; s++) {
                const float* zp = g_zpart + (size_t)s * (BB * GG) + (size_t)gb * GG + gu;
                float2 a = __ldcg((const float2*)(zp));
                float2 f = __ldcg((const float2*)(zp + 512));
                float2 g = __ldcg((const float2*)(zp + 1024));
                float2 o = __ldcg((const float2*)(zp + 1536));
                zi.x += a.x; zi.y += a.y;
                zf.x += f.x; zf.y += f.y;
                zg.x += g.x; zg.y += g.y;
                zo.x += o.x; zo.y += o.y;
            }
            zi.x += bi.x; zi.y += bi.y;
            zf.x += bfg.x; zf.y += bfg.y;
            zg.x += bg.x; zg.y += bg.y;
            zo.x += bo.x; zo.y += bo.y;
            float* cp = g_c + (size_t)gb * UU + gu;
            float2 c = *(const float2*)cp;
            float2 cn, hn;
            cn.x = sigm(zf.x) * c.x + sigm(zi.x) * tanhf(zg.x);
            cn.y = sigm(zf.y) * c.y + sigm(zi.y) * tanhf(zg.y);
            hn.x = sigm(zo.x) * tanhf(cn.x);
            hn.y = sigm(zo.y) * tanhf(cn.y);
            *(float2*)cp = cn;
            size_t hidx = (size_t)(t + 1) * BU + (size_t)gb * UU + gu;
            split2(hn.x, g_hbh[hidx], g_hbl[hidx]);
            split2(hn.y, g_hbh[hidx + 1], g_hbl[hidx + 1]);
        }
        grid_barrier(++gen);
    }
}

// ---------------- Tensorized attention ----------------------------------------
// block = (16 timesteps, one batch b). smem (bytes):
//   sHh [16][528] bf16 @0       (16896)   | aliased later by sW [16][520] f32
//   sHl [16][528] bf16 @16896   (16896)
//   sSc [16][264] f32  @33792   (16896)
//   sA2h[16][272] bf16 @50688   (8704)
//   sA2l[16][272] bf16 @59392   (8704)
#define ATTN_SMEM_BYTES 68096

__global__ __launch_bounds__(256) void attn_kernel() {
    extern __shared__ char smb[];
    bf16* sHh = (bf16*)smb;
    bf16* sHl = (bf16*)(smb + 16896);
    float* sSc = (float*)(smb + 33792);
    bf16* sA2h = (bf16*)(smb + 50688);
    bf16* sA2l = (bf16*)(smb + 59392);
    float* sW = (float*)smb;
    const int tid = threadIdx.x;
    const int wid = tid >> 5, lane = tid & 31;
    const int t0 = blockIdx.x * 16, b = blockIdx.y;
    const bf16* srcbh = g_srcbh + (size_t)b * (SSN * UU);
    const bf16* srcbl = g_srcbl + (size_t)b * (SSN * UU);

    // stage h tile [16t][512u] hi/lo
#pragma unroll
    for (int i = 0; i < 4; i++) {
        int f8 = tid + i * 256;
        int tt = f8 >> 6, c8 = (f8 & 63) * 8;
        size_t hsrc = (size_t)(t0 + tt + 1) * BU + (size_t)b * UU + c8;
        *(uint4*)&sHh[tt * 528 + c8] = *(const uint4*)&g_hbh[hsrc];
        *(uint4*)&sHl[tt * 528 + c8] = *(const uint4*)&g_hbl[hsrc];
    }
    __syncthreads();

    // score: S[16][256] = H @ src^T ; warp wid covers s columns [wid*32, wid*32+32)
    {
        wmma::fragment<wmma::accumulator, 16, 16, 16, float> fsc[2];
#pragma unroll
        for (int j = 0; j < 2; j++) wmma::fill_fragment(fsc[j], 0.f);
#pragma unroll
        for (int kc = 0; kc < 32; kc++) {
            wmma::fragment<wmma::matrix_a, 16, 16, 16, bf16, wmma::row_major> ah, al;
            wmma::load_matrix_sync(ah, &sHh[kc * 16], 528);
            wmma::load_matrix_sync(al, &sHl[kc * 16], 528);
#pragma unroll
            for (int j = 0; j < 2; j++) {
                wmma::fragment<wmma::matrix_b, 16, 16, 16, bf16, wmma::col_major> bh, bl;
                const bf16* bp = srcbh + (size_t)(wid * 32 + j * 16) * UU + kc * 16;
                const bf16* bpl = srcbl + (size_t)(wid * 32 + j * 16) * UU + kc * 16;
                wmma::load_matrix_sync(bh, bp, UU);
                wmma::load_matrix_sync(bl, bpl, UU);
                wmma::mma_sync(fsc[j], ah, bh, fsc[j]);
                wmma::mma_sync(fsc[j], ah, bl, fsc[j]);
                wmma::mma_sync(fsc[j], al, bh, fsc[j]);
            }
        }
#pragma unroll
        for (int j = 0; j < 2; j++)
            wmma::store_matrix_sync(&sSc[wid * 32 + j * 16], fsc[j], 264, wmma::mem_row_major);
    }
    __syncthreads();

    // softmax over s (2 rows per warp); write align as bf16 hi/lo
#pragma unroll
    for (int rr = 0; rr < 2; rr++) {
        int row = wid * 2 + rr;
        float v[8], m = -1e30f;
#pragma unroll
        for (int q = 0; q < 8; q++) { v[q] = sSc[row * 264 + lane + q * 32]; m = fmaxf(m, v[q]); }
#pragma unroll
        for (int o = 16; o > 0; o >>= 1) m = fmaxf(m, __shfl_xor_sync(0xffffffffu, m, o));
        float ssum = 0.f;
#pragma unroll
        for (int q = 0; q < 8; q++) { v[q] = expf(v[q] - m); ssum += v[q]; }
#pragma unroll
        for (int o = 16; o > 0; o >>= 1) ssum += __shfl_xor_sync(0xffffffffu, ssum, o);
        float inv = 1.f / ssum;
#pragma unroll
        for (int q = 0; q < 8; q++) {
            float a = v[q] * inv;
            int cc = lane + q * 32;
            split2(a, sA2h[row * 272 + cc], sA2l[row * 272 + cc]);
        }
    }
    __syncthreads();

    // weighted: W[16][512] = align @ src ; warp wid covers u [wid*64, wid*64+64)
    {
        wmma::fragment<wmma::accumulator, 16, 16, 16, float> fw[4];
#pragma unroll
        for (int j = 0; j < 4; j++) wmma::fill_fragment(fw[j], 0.f);
#pragma unroll
        for (int kc = 0; kc < 16; kc++) {
            wmma::fragment<wmma::matrix_a, 16, 16, 16, bf16, wmma::row_major> a2h, a2l;
            wmma::load_matrix_sync(a2h, &sA2h[kc * 16], 272);
            wmma::load_matrix_sync(a2l, &sA2l[kc * 16], 272);
#pragma unroll
            for (int j = 0; j < 4; j++) {
                wmma::fragment<wmma::matrix_b, 16, 16, 16, bf16, wmma::row_major> bh, bl;
                const bf16* bp = srcbh + (size_t)(kc * 16) * UU + wid * 64 + j * 16;
                const bf16* bpl = srcbl + (size_t)(kc * 16) * UU + wid * 64 + j * 16;
                wmma::load_matrix_sync(bh, bp, UU);
                wmma::load_matrix_sync(bl, bpl, UU);
                wmma::mma_sync(fw[j], a2h, bh, fw[j]);
                wmma::mma_sync(fw[j], a2h, bl, fw[j]);
                wmma::mma_sync(fw[j], a2l, bh, fw[j]);
            }
        }
        __syncthreads();   // h tile reads done; sW aliases it
#pragma unroll
        for (int j = 0; j < 4; j++)
            wmma::store_matrix_sync(&sW[wid * 64 + j * 16], fw[j], 520, wmma::mem_row_major);
    }
    __syncthreads();

    // epilogue: split context to bf16 hi/lo
#pragma unroll
    for (int i = 0; i < 4; i++) {
        int f8 = tid + i * 256;
        int tt = f8 >> 6, c8 = (f8 & 63) * 8;
        size_t base = ((size_t)(t0 + tt) * BB + b) * UU + c8;
#pragma unroll
        for (int e = 0; e < 8; e++)
            split2(sW[tt * 520 + c8 + e], g_wbh[base + e], g_wbl[base + e]);
    }
}

__global__ __launch_bounds__(256) void final_gemm(float* __restrict__ out) {
    WMMA_SMEM
    WMMA_DECLS
    const int t = blockIdx.y, n0 = blockIdx.x * 128;
    for (int k0 = 0; k0 < 1024; k0 += 16) {
        const bf16* Ah;
        const bf16* Al;
        int kc;
        if (k0 < 512) { Ah = g_hbh + (size_t)(t+1) * BU; Al = g_hbl + (size_t)(t+1) * BU; kc = k0; }
        else          { Ah = g_wbh + (size_t)t * BU;     Al = g_wbl + (size_t)t * BU;     kc = k0 - 512; }
        STAGE(Ah + kc, Al + kc, UU,
              g_wah + (size_t)k0 * UU + n0, g_wal + (size_t)k0 * UU + n0, UU)
        WMMA_CHUNK
    }
    WMMA_STORE(out + (size_t)t * UU + n0, (size_t)(TTN * UU))
}

__global__ void tanh_kernel(float* __restrict__ out) {
    int i = blockIdx.x * 256 + threadIdx.x;
    float4 v = ((float4*)out)[i];
    v.x = tanhf(v.x); v.y = tanhf(v.y); v.z = tanhf(v.z); v.w = tanhf(v.w);
    ((float4*)out)[i] = v;
}

extern "C" void kernel_launch(void* const* d_in, const int* in_sizes, int n_in,
                              void* d_out, int out_size) {
    (void)in_sizes; (void)n_in; (void)out_size;
    const float* h0   = (const float*)d_in[0];
    const float* c0   = (const float*)d_in[1];
    const float* src  = (const float*)d_in[2];
    const float* ti   = (const float*)d_in[3];
    const float* W    = (const float*)d_in[4];
    const float* Rk   = (const float*)d_in[5];
    const float* bias = (const float*)d_in[6];
    const float* Wa   = (const float*)d_in[7];
    float* out = (float*)d_out;

    cudaFuncSetAttribute(attn_kernel, cudaFuncAttributeMaxDynamicSharedMemorySize,
                         ATTN_SMEM_BYTES);
    cudaFuncSetAttribute(recurrence_kernel, cudaFuncAttributeMaxDynamicSharedMemorySize,
                         REC_SMEM_BYTES);

    init_kernel<<<256, 256>>>(h0, c0);
    bf16 *wkh, *wkl, *rkh, *rkl, *wah, *wal, *sbh, *sbl;
    cudaGetSymbolAddress((void**)&wkh, g_wkh); cudaGetSymbolAddress((void**)&wkl, g_wkl);
    cudaGetSymbolAddress((void**)&rkh, g_rkh); cudaGetSymbolAddress((void**)&rkl, g_rkl);
    cudaGetSymbolAddress((void**)&wah, g_wah); cudaGetSymbolAddress((void**)&wal, g_wal);
    cudaGetSymbolAddress((void**)&sbh, g_srcbh); cudaGetSymbolAddress((void**)&sbl, g_srcbl);
    cvt_kernel<<<4096, 256>>>(W, wkh, wkl);
    cvt_kernel<<<4096, 256>>>(Rk, rkh, rkl);
    cvt_kernel<<<2048, 256>>>(Wa, wah, wal);
    cvt_kernel<<<65536, 256>>>(src, sbh, sbl);
    cvt_ti_kernel<<<65536, 256>>>(ti);

    xproj_kernel<<<dim3(16, 256), 256>>>();
    recurrence_kernel<<<128, 256, REC_SMEM_BYTES>>>(bias);
    attn_kernel<<<dim3(16, 128), 256, ATTN_SMEM_BYTES>>>();
    final_gemm<<<dim3(4, 256), 256>>>(out);
    tanh_kernel<<<16384, 256>>>(out);
}